// round 16
// baseline (speedup 1.0000x reference)
#include <cuda_runtime.h>
#include <cuda_fp16.h>
#include <cstdint>

#define B   16384
#define D   784
#define H   768
#define C   10
#define K2  1600          // 2*784 + 32 pad (fp16 2-term split)
#define NCH 25            // fc1 K chunks (128B)
#define NC2 12            // fc2/fc3 K chunks: 768*2B / 128B
#define TM  128
#define TN  128
#define NPART 12          // fc4 partials: 6 N-tiles x 2 warp_n

// ---------------- device scratch ----------------
__device__ __align__(128) __half g_A[(size_t)B * K2];    // hi|lo split activations
__device__ __align__(128) __half g_Wb[(size_t)H * K2];   // sign(W1) fp16 x2 (pad 0)
__device__ __align__(128) __half g_a2h[(size_t)B * H];   // fc2 input, fp16 +-1
__device__ __align__(128) __half g_a3h[(size_t)B * H];   // fc3 input, fp16 +-1
__device__ __align__(128) __half g_w2h[H * H];           // sign(W2) fp16
__device__ __align__(128) __half g_w3h[H * H];           // sign(W3) fp16
__device__ __align__(128) float  g_plog[(size_t)NPART * B * C];  // fc4 partial logits
__device__ float g_sc1[H], g_of1[H], g_sc2[H], g_of2[H], g_sc3[H], g_of3[H];

#define SWZ(o) ((o) ^ (((o) >> 3) & 0x70))

__device__ __forceinline__ uint32_t smem_u32(const void* p) {
    uint32_t a;
    asm("{ .reg .u64 t; cvta.to.shared.u64 t, %1; cvt.u32.u64 %0, t; }" : "=r"(a) : "l"(p));
    return a;
}

// ---------------- prep: X split (no div: blockIdx = row) ----------------
__global__ __launch_bounds__(224)
void prep_x(const float* __restrict__ X) {
    const int b = blockIdx.x;
    const int q = threadIdx.x;     // 0..223
    __half* row = &g_A[(size_t)b * K2];
    if (q >= 196) {
        if (q < 204) {
            uint2 z = {0, 0};
            *(uint2*)&row[1568 + (q - 196) * 4] = z;
        }
        return;
    }
    int kg = q * 4;
    float4 xv = *(const float4*)&X[b * D + kg];
    float xs[4] = {xv.x, xv.y, xv.z, xv.w};
    __align__(8) __half hi[4], lo[4];
#pragma unroll
    for (int i = 0; i < 4; i++) {
        float x = xs[i];
        __half h = __float2half_rn(x);
        hi[i] = h;
        lo[i] = __float2half_rn(x - __half2float(h));
    }
    *(uint2*)&row[kg]       = *(uint2*)hi;
    *(uint2*)&row[784 + kg] = *(uint2*)lo;
}

// ---------------- prep: sign(W1) (no div: blockIdx = row) ----------------
__global__ __launch_bounds__(224)
void prep_w1(const float* __restrict__ W1) {
    const int j = blockIdx.x;
    const int q = threadIdx.x;
    __half* row = &g_Wb[(size_t)j * K2];
    if (q >= 196) {
        if (q < 204) {
            uint2 z = {0, 0};
            *(uint2*)&row[1568 + (q - 196) * 4] = z;
        }
        return;
    }
    int kg = q * 4;
    float4 wv = *(const float4*)&W1[j * D + kg];
    __align__(8) __half o[4];
    o[0] = __float2half(wv.x >= 0.f ? 1.f : -1.f);
    o[1] = __float2half(wv.y >= 0.f ? 1.f : -1.f);
    o[2] = __float2half(wv.z >= 0.f ? 1.f : -1.f);
    o[3] = __float2half(wv.w >= 0.f ? 1.f : -1.f);
    *(uint2*)&row[kg]       = *(uint2*)o;
    *(uint2*)&row[784 + kg] = *(uint2*)o;
}

// ---------------- prep: sign(W2), sign(W3), BN scales (linear) ----------------
__global__ void prep_w23s(const float* __restrict__ W2, const float* __restrict__ W3,
                          const float* b1, const float* g1, const float* m1, const float* be1, const float* v1,
                          const float* b2, const float* g2, const float* m2, const float* be2, const float* v2,
                          const float* b3, const float* g3, const float* m3, const float* be3, const float* v3) {
    int idx = blockIdx.x * blockDim.x + threadIdx.x;
    if (idx < 2 * H * 192) {
        int which = idx >= H * 192;
        int q = which ? idx - H * 192 : idx;
        const float* W = which ? W3 : W2;
        __half* dst = which ? g_w3h : g_w2h;
        int kg = q * 4;
        float4 wv = *(const float4*)&W[kg];
        __align__(8) __half o[4];
        o[0] = __float2half(wv.x >= 0.f ? 1.f : -1.f);
        o[1] = __float2half(wv.y >= 0.f ? 1.f : -1.f);
        o[2] = __float2half(wv.z >= 0.f ? 1.f : -1.f);
        o[3] = __float2half(wv.w >= 0.f ? 1.f : -1.f);
        *(uint2*)&dst[kg] = *(uint2*)o;
        return;
    }
    int j = idx - 2 * H * 192;
    if (j >= H) return;
    float s1 = g1[j] * (float)(1.0 / sqrt((double)(v1[j] + 1e-5f)));
    float s2 = g2[j] * (float)(1.0 / sqrt((double)(v2[j] + 1e-5f)));
    float s3 = g3[j] * (float)(1.0 / sqrt((double)(v3[j] + 1e-5f)));
    g_sc1[j] = s1; g_of1[j] = (b1[j] - m1[j]) * s1 + be1[j];
    g_sc2[j] = s2; g_of2[j] = (b2[j] - m2[j]) * s2 + be2[j];
    g_sc3[j] = s3; g_of3[j] = (b3[j] - m3[j]) * s3 + be3[j];
}

// ================= GEMM tiles: 4 warps, warp tile 64x64, CTA 128x128 =========
#define GEMM_SMEM 66560
#define A_OFF(b) (1024u + (b) * 16384u)
#define B_OFF(b) (33792u + (b) * 16384u)

// ---------------- fc1: fp32-acc fp16 GEMM, now 3 CTAs/SM --------------------
__global__ __launch_bounds__(128, 3)
void fc1_gemm() {
    extern __shared__ char smem[];
    const uint32_t sb = smem_u32(smem);
    const int tid = threadIdx.x;
    const int wid = tid >> 5, lane = tid & 31;
    const int warp_m = wid >> 1, warp_n = wid & 1;
    const int bn = blockIdx.x * TN, bm = blockIdx.y * TM;

    float* ssc = (float*)(smem);
    float* sof = (float*)(smem + 512);
    ssc[tid] = g_sc1[bn + tid]; sof[tid] = g_of1[bn + tid];

    const char* Abase = (const char*)g_A  + (size_t)bm * (K2 * 2);
    const char* Bbase = (const char*)g_Wb + (size_t)bn * (K2 * 2);

    float acc[4][8][4];
#pragma unroll
    for (int i = 0; i < 4; i++)
#pragma unroll
        for (int j = 0; j < 8; j++)
#pragma unroll
            for (int c = 0; c < 4; c++) acc[i][j][c] = 0.f;

    auto load_stage = [&](int s, int buf) {
        size_t kb = (size_t)s * 128;
        uint32_t adst = sb + A_OFF(buf), bdst = sb + B_OFF(buf);
#pragma unroll
        for (int i = 0; i < 8; i++) {
            int idx = i * 128 + tid;
            int row = idx >> 3, c = idx & 7;
            uint32_t off = SWZ((uint32_t)(row * 128 + c * 16));
            const char* srcA = Abase + (size_t)row * (K2 * 2) + kb + c * 16;
            const char* srcB = Bbase + (size_t)row * (K2 * 2) + kb + c * 16;
            asm volatile("cp.async.cg.shared.global [%0], [%1], 16;" :: "r"(adst + off), "l"(srcA));
            asm volatile("cp.async.cg.shared.global [%0], [%1], 16;" :: "r"(bdst + off), "l"(srcB));
        }
        asm volatile("cp.async.commit_group;");
    };

    auto compute = [&](int buf) {
        uint32_t ab = sb + A_OFF(buf), bb = sb + B_OFF(buf);
#pragma unroll
        for (int ks = 0; ks < 4; ks++) {
            uint32_t a[4][4], bf[4][4];
            const int kk = ks * 16 + (lane >> 4) * 8;
            const int mrow = warp_m * 64 + (lane & 15);
            const int nrow = warp_n * 64 + (lane & 15);
#pragma unroll
            for (int mf = 0; mf < 4; mf++) {
                uint32_t addr = ab + SWZ((uint32_t)((mrow + mf * 16) * 128 + kk * 2));
                asm volatile("ldmatrix.sync.aligned.m8n8.x4.shared.b16 {%0,%1,%2,%3}, [%4];"
                    : "=r"(a[mf][0]), "=r"(a[mf][1]), "=r"(a[mf][2]), "=r"(a[mf][3]) : "r"(addr));
            }
#pragma unroll
            for (int p = 0; p < 4; p++) {
                uint32_t addr = bb + SWZ((uint32_t)((nrow + p * 16) * 128 + kk * 2));
                asm volatile("ldmatrix.sync.aligned.m8n8.x4.shared.b16 {%0,%1,%2,%3}, [%4];"
                    : "=r"(bf[p][0]), "=r"(bf[p][1]), "=r"(bf[p][2]), "=r"(bf[p][3]) : "r"(addr));
            }
#pragma unroll
            for (int mf = 0; mf < 4; mf++)
#pragma unroll
                for (int nf = 0; nf < 8; nf++) {
                    uint32_t b0 = bf[nf >> 1][nf & 1], b1 = bf[nf >> 1][(nf & 1) + 2];
                    asm volatile(
                        "mma.sync.aligned.m16n8k16.row.col.f32.f16.f16.f32 "
                        "{%0,%1,%2,%3}, {%4,%5,%6,%7}, {%8,%9}, {%0,%1,%2,%3};"
                        : "+f"(acc[mf][nf][0]), "+f"(acc[mf][nf][1]),
                          "+f"(acc[mf][nf][2]), "+f"(acc[mf][nf][3])
                        : "r"(a[mf][0]), "r"(a[mf][1]), "r"(a[mf][2]), "r"(a[mf][3]),
                          "r"(b0), "r"(b1));
                }
        }
    };

    load_stage(0, 0);
    for (int s = 0; s < NCH; s++) {
        if (s + 1 < NCH) load_stage(s + 1, (s + 1) & 1);
        if (s + 1 < NCH) asm volatile("cp.async.wait_group 1;");
        else             asm volatile("cp.async.wait_group 0;");
        __syncthreads();
        compute(s & 1);
        __syncthreads();
    }

    const int tg = lane & 3, gid = lane >> 2;
    const __half hp1 = __float2half(1.f), hm1 = __float2half(-1.f);
#pragma unroll
    for (int mf = 0; mf < 4; mf++) {
        int row = bm + warp_m * 64 + mf * 16 + gid;
#pragma unroll
        for (int nf = 0; nf < 8; nf++) {
            int cl = warp_n * 64 + nf * 8 + tg * 2;
            int col = bn + cl;
            float f00 = fmaf(acc[mf][nf][0], ssc[cl],     sof[cl]);
            float f01 = fmaf(acc[mf][nf][1], ssc[cl + 1], sof[cl + 1]);
            float f10 = fmaf(acc[mf][nf][2], ssc[cl],     sof[cl]);
            float f11 = fmaf(acc[mf][nf][3], ssc[cl + 1], sof[cl + 1]);
            __half2 hA = __halves2half2(f00 >= 0.f ? hp1 : hm1, f01 >= 0.f ? hp1 : hm1);
            __half2 hB = __halves2half2(f10 >= 0.f ? hp1 : hm1, f11 >= 0.f ? hp1 : hm1);
            *(__half2*)&g_a2h[(size_t)row * H + col]       = hA;
            *(__half2*)&g_a2h[(size_t)(row + 8) * H + col] = hB;
        }
    }
}

// ---------------- fc2: fp16-acc GEMM, epilogue -> fp16 +-1 (g_a3h) ----------
__global__ __launch_bounds__(128, 3)
void fc2_gemm() {
    extern __shared__ char smem[];
    const uint32_t sb = smem_u32(smem);
    const int tid = threadIdx.x;
    const int wid = tid >> 5, lane = tid & 31;
    const int warp_m = wid >> 1, warp_n = wid & 1;
    const int bn = blockIdx.x * TN, bm = blockIdx.y * TM;

    float* ssc = (float*)(smem);
    float* sof = (float*)(smem + 512);
    ssc[tid] = g_sc2[bn + tid]; sof[tid] = g_of2[bn + tid];

    const char* Abase = (const char*)g_a2h + (size_t)bm * (H * 2);
    const char* Bbase = (const char*)g_w2h + (size_t)bn * (H * 2);

    uint32_t acc[4][8][2];
#pragma unroll
    for (int i = 0; i < 4; i++)
#pragma unroll
        for (int j = 0; j < 8; j++) { acc[i][j][0] = 0u; acc[i][j][1] = 0u; }

    auto load_stage = [&](int s, int buf) {
        size_t kb = (size_t)s * 128;
        uint32_t adst = sb + A_OFF(buf), bdst = sb + B_OFF(buf);
#pragma unroll
        for (int i = 0; i < 8; i++) {
            int idx = i * 128 + tid;
            int row = idx >> 3, c = idx & 7;
            uint32_t off = SWZ((uint32_t)(row * 128 + c * 16));
            const char* srcA = Abase + (size_t)row * (H * 2) + kb + c * 16;
            const char* srcB = Bbase + (size_t)row * (H * 2) + kb + c * 16;
            asm volatile("cp.async.cg.shared.global [%0], [%1], 16;" :: "r"(adst + off), "l"(srcA));
            asm volatile("cp.async.cg.shared.global [%0], [%1], 16;" :: "r"(bdst + off), "l"(srcB));
        }
        asm volatile("cp.async.commit_group;");
    };

    auto compute = [&](int buf) {
        uint32_t ab = sb + A_OFF(buf), bb = sb + B_OFF(buf);
#pragma unroll
        for (int ks = 0; ks < 4; ks++) {
            uint32_t a[4][4], bf[4][4];
            const int kk = ks * 16 + (lane >> 4) * 8;
            const int mrow = warp_m * 64 + (lane & 15);
            const int nrow = warp_n * 64 + (lane & 15);
#pragma unroll
            for (int mf = 0; mf < 4; mf++) {
                uint32_t addr = ab + SWZ((uint32_t)((mrow + mf * 16) * 128 + kk * 2));
                asm volatile("ldmatrix.sync.aligned.m8n8.x4.shared.b16 {%0,%1,%2,%3}, [%4];"
                    : "=r"(a[mf][0]), "=r"(a[mf][1]), "=r"(a[mf][2]), "=r"(a[mf][3]) : "r"(addr));
            }
#pragma unroll
            for (int p = 0; p < 4; p++) {
                uint32_t addr = bb + SWZ((uint32_t)((nrow + p * 16) * 128 + kk * 2));
                asm volatile("ldmatrix.sync.aligned.m8n8.x4.shared.b16 {%0,%1,%2,%3}, [%4];"
                    : "=r"(bf[p][0]), "=r"(bf[p][1]), "=r"(bf[p][2]), "=r"(bf[p][3]) : "r"(addr));
            }
#pragma unroll
            for (int mf = 0; mf < 4; mf++)
#pragma unroll
                for (int nf = 0; nf < 8; nf++) {
                    uint32_t b0 = bf[nf >> 1][nf & 1], b1 = bf[nf >> 1][(nf & 1) + 2];
                    asm volatile(
                        "mma.sync.aligned.m16n8k16.row.col.f16.f16.f16.f16 "
                        "{%0,%1}, {%2,%3,%4,%5}, {%6,%7}, {%0,%1};"
                        : "+r"(acc[mf][nf][0]), "+r"(acc[mf][nf][1])
                        : "r"(a[mf][0]), "r"(a[mf][1]), "r"(a[mf][2]), "r"(a[mf][3]),
                          "r"(b0), "r"(b1));
                }
        }
    };

    load_stage(0, 0);
    for (int s = 0; s < NC2; s++) {
        if (s + 1 < NC2) load_stage(s + 1, (s + 1) & 1);
        if (s + 1 < NC2) asm volatile("cp.async.wait_group 1;");
        else             asm volatile("cp.async.wait_group 0;");
        __syncthreads();
        compute(s & 1);
        __syncthreads();
    }

    const int tg = lane & 3, gid = lane >> 2;
    const __half hp1 = __float2half(1.f), hm1 = __float2half(-1.f);
#pragma unroll
    for (int mf = 0; mf < 4; mf++) {
        int row = bm + warp_m * 64 + mf * 16 + gid;
#pragma unroll
        for (int nf = 0; nf < 8; nf++) {
            int cl = warp_n * 64 + nf * 8 + tg * 2;
            int col = bn + cl;
            float2 fa = __half22float2(*(__half2*)&acc[mf][nf][0]);
            float2 fb = __half22float2(*(__half2*)&acc[mf][nf][1]);
            float f00 = fmaf(fa.x, ssc[cl],     sof[cl]);
            float f01 = fmaf(fa.y, ssc[cl + 1], sof[cl + 1]);
            float f10 = fmaf(fb.x, ssc[cl],     sof[cl]);
            float f11 = fmaf(fb.y, ssc[cl + 1], sof[cl + 1]);
            __half2 hA = __halves2half2(f00 >= 0.f ? hp1 : hm1, f01 >= 0.f ? hp1 : hm1);
            __half2 hB = __halves2half2(f10 >= 0.f ? hp1 : hm1, f11 >= 0.f ? hp1 : hm1);
            *(__half2*)&g_a3h[(size_t)row * H + col]       = hA;
            *(__half2*)&g_a3h[(size_t)(row + 8) * H + col] = hB;
        }
    }
}

// ---------------- fc3: fp16-acc GEMM + fused partial-fc4 epilogue -----------
#define FC3_SMEM (66560 + C * TN * 4)   // + W4 tile [10][128]

__global__ __launch_bounds__(128, 3)
void fc3_gemm(const float* __restrict__ W4) {
    extern __shared__ char smem[];
    const uint32_t sb = smem_u32(smem);
    const int tid = threadIdx.x;
    const int wid = tid >> 5, lane = tid & 31;
    const int warp_m = wid >> 1, warp_n = wid & 1;
    const int bn = blockIdx.x * TN, bm = blockIdx.y * TM;

    float* ssc = (float*)(smem);
    float* sof = (float*)(smem + 512);
    float* sW4 = (float*)(smem + 66560);
    ssc[tid] = g_sc3[bn + tid]; sof[tid] = g_of3[bn + tid];
#pragma unroll
    for (int i = tid; i < C * TN; i += 128) {
        int c = i >> 7, cc = i & 127;
        sW4[i] = W4[c * H + bn + cc];
    }

    const char* Abase = (const char*)g_a3h + (size_t)bm * (H * 2);
    const char* Bbase = (const char*)g_w3h + (size_t)bn * (H * 2);

    uint32_t acc[4][8][2];
#pragma unroll
    for (int i = 0; i < 4; i++)
#pragma unroll
        for (int j = 0; j < 8; j++) { acc[i][j][0] = 0u; acc[i][j][1] = 0u; }

    auto load_stage = [&](int s, int buf) {
        size_t kb = (size_t)s * 128;
        uint32_t adst = sb + A_OFF(buf), bdst = sb + B_OFF(buf);
#pragma unroll
        for (int i = 0; i < 8; i++) {
            int idx = i * 128 + tid;
            int row = idx >> 3, c = idx & 7;
            uint32_t off = SWZ((uint32_t)(row * 128 + c * 16));
            const char* srcA = Abase + (size_t)row * (H * 2) + kb + c * 16;
            const char* srcB = Bbase + (size_t)row * (H * 2) + kb + c * 16;
            asm volatile("cp.async.cg.shared.global [%0], [%1], 16;" :: "r"(adst + off), "l"(srcA));
            asm volatile("cp.async.cg.shared.global [%0], [%1], 16;" :: "r"(bdst + off), "l"(srcB));
        }
        asm volatile("cp.async.commit_group;");
    };

    auto compute = [&](int buf) {
        uint32_t ab = sb + A_OFF(buf), bb = sb + B_OFF(buf);
#pragma unroll
        for (int ks = 0; ks < 4; ks++) {
            uint32_t a[4][4], bf[4][4];
            const int kk = ks * 16 + (lane >> 4) * 8;
            const int mrow = warp_m * 64 + (lane & 15);
            const int nrow = warp_n * 64 + (lane & 15);
#pragma unroll
            for (int mf = 0; mf < 4; mf++) {
                uint32_t addr = ab + SWZ((uint32_t)((mrow + mf * 16) * 128 + kk * 2));
                asm volatile("ldmatrix.sync.aligned.m8n8.x4.shared.b16 {%0,%1,%2,%3}, [%4];"
                    : "=r"(a[mf][0]), "=r"(a[mf][1]), "=r"(a[mf][2]), "=r"(a[mf][3]) : "r"(addr));
            }
#pragma unroll
            for (int p = 0; p < 4; p++) {
                uint32_t addr = bb + SWZ((uint32_t)((nrow + p * 16) * 128 + kk * 2));
                asm volatile("ldmatrix.sync.aligned.m8n8.x4.shared.b16 {%0,%1,%2,%3}, [%4];"
                    : "=r"(bf[p][0]), "=r"(bf[p][1]), "=r"(bf[p][2]), "=r"(bf[p][3]) : "r"(addr));
            }
#pragma unroll
            for (int mf = 0; mf < 4; mf++)
#pragma unroll
                for (int nf = 0; nf < 8; nf++) {
                    uint32_t b0 = bf[nf >> 1][nf & 1], b1 = bf[nf >> 1][(nf & 1) + 2];
                    asm volatile(
                        "mma.sync.aligned.m16n8k16.row.col.f16.f16.f16.f16 "
                        "{%0,%1}, {%2,%3,%4,%5}, {%6,%7}, {%0,%1};"
                        : "+r"(acc[mf][nf][0]), "+r"(acc[mf][nf][1])
                        : "r"(a[mf][0]), "r"(a[mf][1]), "r"(a[mf][2]), "r"(a[mf][3]),
                          "r"(b0), "r"(b1));
                }
        }
    };

    load_stage(0, 0);
    for (int s = 0; s < NC2; s++) {
        if (s + 1 < NC2) load_stage(s + 1, (s + 1) & 1);
        if (s + 1 < NC2) asm volatile("cp.async.wait_group 1;");
        else             asm volatile("cp.async.wait_group 0;");
        __syncthreads();
        compute(s & 1);
        __syncthreads();
    }

    // epilogue: BN + hardtanh + partial fc4 dot over this CTA's 128 columns
    const int tg = lane & 3, gid = lane >> 2;
    const size_t pbase = (size_t)(blockIdx.x * 2 + warp_n) * B * C;
#pragma unroll
    for (int mf = 0; mf < 4; mf++) {
        int r0 = bm + warp_m * 64 + mf * 16 + gid;
        float plg0[C], plg1[C];
#pragma unroll
        for (int c = 0; c < C; c++) { plg0[c] = 0.f; plg1[c] = 0.f; }
#pragma unroll
        for (int nf = 0; nf < 8; nf++) {
            int cl = warp_n * 64 + nf * 8 + tg * 2;
            float2 fa = __half22float2(*(__half2*)&acc[mf][nf][0]);
            float2 fb = __half22float2(*(__half2*)&acc[mf][nf][1]);
            float h00 = fminf(fmaxf(fmaf(fa.x, ssc[cl],     sof[cl]),     -1.f), 1.f);
            float h01 = fminf(fmaxf(fmaf(fa.y, ssc[cl + 1], sof[cl + 1]), -1.f), 1.f);
            float h10 = fminf(fmaxf(fmaf(fb.x, ssc[cl],     sof[cl]),     -1.f), 1.f);
            float h11 = fminf(fmaxf(fmaf(fb.y, ssc[cl + 1], sof[cl + 1]), -1.f), 1.f);
#pragma unroll
            for (int c = 0; c < C; c++) {
                float w0 = sW4[c * TN + cl], w1 = sW4[c * TN + cl + 1];
                plg0[c] += h00 * w0 + h01 * w1;
                plg1[c] += h10 * w0 + h11 * w1;
            }
        }
#pragma unroll
        for (int c = 0; c < C; c++) {
            plg0[c] += __shfl_xor_sync(0xffffffffu, plg0[c], 1);
            plg0[c] += __shfl_xor_sync(0xffffffffu, plg0[c], 2);
            plg1[c] += __shfl_xor_sync(0xffffffffu, plg1[c], 1);
            plg1[c] += __shfl_xor_sync(0xffffffffu, plg1[c], 2);
        }
        if (tg == 0) {
#pragma unroll
            for (int c = 0; c < C; c++) {
                g_plog[pbase + (size_t)r0 * C + c]       = plg0[c];
                g_plog[pbase + (size_t)(r0 + 8) * C + c] = plg1[c];
            }
        }
    }
}

// ---------------- fc4_soft: sum 12 partials + b4 + log_softmax --------------
__global__ __launch_bounds__(256)
void fc4_soft(const float* __restrict__ b4, float* __restrict__ out) {
    int w = blockIdx.x * 256 + threadIdx.x;
    float lg[C];
#pragma unroll
    for (int c = 0; c < C; c++) lg[c] = b4[c];
#pragma unroll
    for (int p = 0; p < NPART; p++) {
        const float* src = &g_plog[(size_t)p * B * C + (size_t)w * C];
#pragma unroll
        for (int c2 = 0; c2 < C / 2; c2++) {
            float2 v = *(const float2*)&src[c2 * 2];
            lg[c2 * 2]     += v.x;
            lg[c2 * 2 + 1] += v.y;
        }
    }
    float mx = -3.402823466e+38f;
#pragma unroll
    for (int c = 0; c < C; c++) mx = fmaxf(mx, lg[c]);
    float s = 0.f;
#pragma unroll
    for (int c = 0; c < C; c++) s += expf(lg[c] - mx);
    float lse = logf(s);
#pragma unroll
    for (int c2 = 0; c2 < C / 2; c2++) {
        float2 v;
        v.x = lg[c2 * 2] - mx - lse;
        v.y = lg[c2 * 2 + 1] - mx - lse;
        *(float2*)&out[(size_t)w * C + c2 * 2] = v;
    }
}

// ---------------- launch (fc1_gemm is launch #4 -> profiled) ----------------
extern "C" void kernel_launch(void* const* d_in, const int* in_sizes, int n_in,
                              void* d_out, int out_size) {
    const float* x   = (const float*)d_in[0];
    const float* W1  = (const float*)d_in[1];
    const float* b1  = (const float*)d_in[2];
    const float* W2  = (const float*)d_in[3];
    const float* b2  = (const float*)d_in[4];
    const float* W3  = (const float*)d_in[5];
    const float* b3  = (const float*)d_in[6];
    const float* W4  = (const float*)d_in[7];
    const float* b4  = (const float*)d_in[8];
    const float* g1  = (const float*)d_in[9];
    const float* be1 = (const float*)d_in[10];
    const float* m1  = (const float*)d_in[11];
    const float* v1  = (const float*)d_in[12];
    const float* g2  = (const float*)d_in[13];
    const float* be2 = (const float*)d_in[14];
    const float* m2  = (const float*)d_in[15];
    const float* v2  = (const float*)d_in[16];
    const float* g3  = (const float*)d_in[17];
    const float* be3 = (const float*)d_in[18];
    const float* m3  = (const float*)d_in[19];
    const float* v3  = (const float*)d_in[20];
    float* out = (float*)d_out;

    cudaFuncSetAttribute(fc1_gemm, cudaFuncAttributeMaxDynamicSharedMemorySize, GEMM_SMEM);
    cudaFuncSetAttribute(fc2_gemm, cudaFuncAttributeMaxDynamicSharedMemorySize, GEMM_SMEM);
    cudaFuncSetAttribute(fc3_gemm, cudaFuncAttributeMaxDynamicSharedMemorySize, FC3_SMEM);

    int w23Threads = 2 * H * 192 + H;
    prep_w23s<<<(w23Threads + 255) / 256, 256>>>(W2, W3,
        b1, g1, m1, be1, v1, b2, g2, m2, be2, v2, b3, g3, m3, be3, v3);
    prep_x<<<B, 224>>>(x);
    prep_w1<<<H, 224>>>(W1);

    fc1_gemm<<<dim3(H / TN, B / TM), 128, GEMM_SMEM>>>();     // launch #4 (profiled)
    fc2_gemm<<<dim3(H / TN, B / TM), 128, GEMM_SMEM>>>();
    fc3_gemm<<<dim3(H / TN, B / TM), 128, FC3_SMEM>>>(W4);
    fc4_soft<<<B / 256, 256>>>(b4, out);
}

// round 17
// speedup vs baseline: 1.1149x; 1.1149x over previous
#include <cuda_runtime.h>
#include <cuda_fp16.h>
#include <cstdint>

#define B   16384
#define D   784
#define H   768
#define C   10
#define K2  1600          // 2*784 + 32 pad (fp16 2-term split)
#define NCH 25            // fc1 K chunks (128B)
#define NC2 12            // fc2/fc3 K chunks: 768*2B / 128B
#define TM  128
#define TN  128
#define NPART 12          // fc4 partials: 6 N-tiles x 2 warp_n

// ---------------- device scratch ----------------
__device__ __align__(128) __half g_A[(size_t)B * K2];    // hi|lo split activations
__device__ __align__(128) __half g_Wb[(size_t)H * K2];   // sign(W1) fp16 x2 (pad 0)
__device__ __align__(128) __half g_a2h[(size_t)B * H];   // fc2 input, fp16 +-1
__device__ __align__(128) __half g_a3h[(size_t)B * H];   // fc3 input, fp16 +-1
__device__ __align__(128) __half g_w2h[H * H];           // sign(W2) fp16
__device__ __align__(128) __half g_w3h[H * H];           // sign(W3) fp16
__device__ __align__(128) float  g_plog[(size_t)NPART * B * C];  // fc4 partial logits
__device__ float g_sc1[H], g_of1[H], g_sc2[H], g_of2[H], g_sc3[H], g_of3[H];

#define SWZ(o) ((o) ^ (((o) >> 3) & 0x70))

__device__ __forceinline__ uint32_t smem_u32(const void* p) {
    uint32_t a;
    asm("{ .reg .u64 t; cvta.to.shared.u64 t, %1; cvt.u32.u64 %0, t; }" : "=r"(a) : "l"(p));
    return a;
}

// ---------------- prep: X split (no div: blockIdx = row) ----------------
__global__ __launch_bounds__(224)
void prep_x(const float* __restrict__ X) {
    const int b = blockIdx.x;
    const int q = threadIdx.x;     // 0..223
    __half* row = &g_A[(size_t)b * K2];
    if (q >= 196) {
        if (q < 204) {
            uint2 z = {0, 0};
            *(uint2*)&row[1568 + (q - 196) * 4] = z;
        }
        return;
    }
    int kg = q * 4;
    float4 xv = *(const float4*)&X[b * D + kg];
    float xs[4] = {xv.x, xv.y, xv.z, xv.w};
    __align__(8) __half hi[4], lo[4];
#pragma unroll
    for (int i = 0; i < 4; i++) {
        float x = xs[i];
        __half h = __float2half_rn(x);
        hi[i] = h;
        lo[i] = __float2half_rn(x - __half2float(h));
    }
    *(uint2*)&row[kg]       = *(uint2*)hi;
    *(uint2*)&row[784 + kg] = *(uint2*)lo;
}

// ---------------- prep: sign(W1) (no div: blockIdx = row) ----------------
__global__ __launch_bounds__(224)
void prep_w1(const float* __restrict__ W1) {
    const int j = blockIdx.x;
    const int q = threadIdx.x;
    __half* row = &g_Wb[(size_t)j * K2];
    if (q >= 196) {
        if (q < 204) {
            uint2 z = {0, 0};
            *(uint2*)&row[1568 + (q - 196) * 4] = z;
        }
        return;
    }
    int kg = q * 4;
    float4 wv = *(const float4*)&W1[j * D + kg];
    __align__(8) __half o[4];
    o[0] = __float2half(wv.x >= 0.f ? 1.f : -1.f);
    o[1] = __float2half(wv.y >= 0.f ? 1.f : -1.f);
    o[2] = __float2half(wv.z >= 0.f ? 1.f : -1.f);
    o[3] = __float2half(wv.w >= 0.f ? 1.f : -1.f);
    *(uint2*)&row[kg]       = *(uint2*)o;
    *(uint2*)&row[784 + kg] = *(uint2*)o;
}

// ---------------- prep: sign(W2), sign(W3), BN scales (linear) ----------------
__global__ void prep_w23s(const float* __restrict__ W2, const float* __restrict__ W3,
                          const float* b1, const float* g1, const float* m1, const float* be1, const float* v1,
                          const float* b2, const float* g2, const float* m2, const float* be2, const float* v2,
                          const float* b3, const float* g3, const float* m3, const float* be3, const float* v3) {
    int idx = blockIdx.x * blockDim.x + threadIdx.x;
    if (idx < 2 * H * 192) {
        int which = idx >= H * 192;
        int q = which ? idx - H * 192 : idx;
        const float* W = which ? W3 : W2;
        __half* dst = which ? g_w3h : g_w2h;
        int kg = q * 4;
        float4 wv = *(const float4*)&W[kg];
        __align__(8) __half o[4];
        o[0] = __float2half(wv.x >= 0.f ? 1.f : -1.f);
        o[1] = __float2half(wv.y >= 0.f ? 1.f : -1.f);
        o[2] = __float2half(wv.z >= 0.f ? 1.f : -1.f);
        o[3] = __float2half(wv.w >= 0.f ? 1.f : -1.f);
        *(uint2*)&dst[kg] = *(uint2*)o;
        return;
    }
    int j = idx - 2 * H * 192;
    if (j >= H) return;
    float s1 = g1[j] * (float)(1.0 / sqrt((double)(v1[j] + 1e-5f)));
    float s2 = g2[j] * (float)(1.0 / sqrt((double)(v2[j] + 1e-5f)));
    float s3 = g3[j] * (float)(1.0 / sqrt((double)(v3[j] + 1e-5f)));
    g_sc1[j] = s1; g_of1[j] = (b1[j] - m1[j]) * s1 + be1[j];
    g_sc2[j] = s2; g_of2[j] = (b2[j] - m2[j]) * s2 + be2[j];
    g_sc3[j] = s3; g_of3[j] = (b3[j] - m3[j]) * s3 + be3[j];
}

// ================= GEMM tiles: 4 warps, warp tile 64x64, CTA 128x128 =========
#define GEMM_SMEM 66560
#define A_OFF(b) (1024u + (b) * 16384u)
#define B_OFF(b) (33792u + (b) * 16384u)

// ---------------- fc1: fp32-acc fp16 GEMM (R14 config: 2 CTAs/SM) -----------
__global__ __launch_bounds__(128, 2)
void fc1_gemm() {
    extern __shared__ char smem[];
    const uint32_t sb = smem_u32(smem);
    const int tid = threadIdx.x;
    const int wid = tid >> 5, lane = tid & 31;
    const int warp_m = wid >> 1, warp_n = wid & 1;
    const int bn = blockIdx.x * TN, bm = blockIdx.y * TM;

    float* ssc = (float*)(smem);
    float* sof = (float*)(smem + 512);
    ssc[tid] = g_sc1[bn + tid]; sof[tid] = g_of1[bn + tid];

    const char* Abase = (const char*)g_A  + (size_t)bm * (K2 * 2);
    const char* Bbase = (const char*)g_Wb + (size_t)bn * (K2 * 2);

    float acc[4][8][4];
#pragma unroll
    for (int i = 0; i < 4; i++)
#pragma unroll
        for (int j = 0; j < 8; j++)
#pragma unroll
            for (int c = 0; c < 4; c++) acc[i][j][c] = 0.f;

    auto load_stage = [&](int s, int buf) {
        size_t kb = (size_t)s * 128;
        uint32_t adst = sb + A_OFF(buf), bdst = sb + B_OFF(buf);
#pragma unroll
        for (int i = 0; i < 8; i++) {
            int idx = i * 128 + tid;
            int row = idx >> 3, c = idx & 7;
            uint32_t off = SWZ((uint32_t)(row * 128 + c * 16));
            const char* srcA = Abase + (size_t)row * (K2 * 2) + kb + c * 16;
            const char* srcB = Bbase + (size_t)row * (K2 * 2) + kb + c * 16;
            asm volatile("cp.async.cg.shared.global [%0], [%1], 16;" :: "r"(adst + off), "l"(srcA));
            asm volatile("cp.async.cg.shared.global [%0], [%1], 16;" :: "r"(bdst + off), "l"(srcB));
        }
        asm volatile("cp.async.commit_group;");
    };

    auto compute = [&](int buf) {
        uint32_t ab = sb + A_OFF(buf), bb = sb + B_OFF(buf);
#pragma unroll
        for (int ks = 0; ks < 4; ks++) {
            uint32_t a[4][4], bf[4][4];
            const int kk = ks * 16 + (lane >> 4) * 8;
            const int mrow = warp_m * 64 + (lane & 15);
            const int nrow = warp_n * 64 + (lane & 15);
#pragma unroll
            for (int mf = 0; mf < 4; mf++) {
                uint32_t addr = ab + SWZ((uint32_t)((mrow + mf * 16) * 128 + kk * 2));
                asm volatile("ldmatrix.sync.aligned.m8n8.x4.shared.b16 {%0,%1,%2,%3}, [%4];"
                    : "=r"(a[mf][0]), "=r"(a[mf][1]), "=r"(a[mf][2]), "=r"(a[mf][3]) : "r"(addr));
            }
#pragma unroll
            for (int p = 0; p < 4; p++) {
                uint32_t addr = bb + SWZ((uint32_t)((nrow + p * 16) * 128 + kk * 2));
                asm volatile("ldmatrix.sync.aligned.m8n8.x4.shared.b16 {%0,%1,%2,%3}, [%4];"
                    : "=r"(bf[p][0]), "=r"(bf[p][1]), "=r"(bf[p][2]), "=r"(bf[p][3]) : "r"(addr));
            }
#pragma unroll
            for (int mf = 0; mf < 4; mf++)
#pragma unroll
                for (int nf = 0; nf < 8; nf++) {
                    uint32_t b0 = bf[nf >> 1][nf & 1], b1 = bf[nf >> 1][(nf & 1) + 2];
                    asm volatile(
                        "mma.sync.aligned.m16n8k16.row.col.f32.f16.f16.f32 "
                        "{%0,%1,%2,%3}, {%4,%5,%6,%7}, {%8,%9}, {%0,%1,%2,%3};"
                        : "+f"(acc[mf][nf][0]), "+f"(acc[mf][nf][1]),
                          "+f"(acc[mf][nf][2]), "+f"(acc[mf][nf][3])
                        : "r"(a[mf][0]), "r"(a[mf][1]), "r"(a[mf][2]), "r"(a[mf][3]),
                          "r"(b0), "r"(b1));
                }
        }
    };

    load_stage(0, 0);
    for (int s = 0; s < NCH; s++) {
        if (s + 1 < NCH) load_stage(s + 1, (s + 1) & 1);
        if (s + 1 < NCH) asm volatile("cp.async.wait_group 1;");
        else             asm volatile("cp.async.wait_group 0;");
        __syncthreads();
        compute(s & 1);
        __syncthreads();
    }

    const int tg = lane & 3, gid = lane >> 2;
    const __half hp1 = __float2half(1.f), hm1 = __float2half(-1.f);
#pragma unroll
    for (int mf = 0; mf < 4; mf++) {
        int row = bm + warp_m * 64 + mf * 16 + gid;
#pragma unroll
        for (int nf = 0; nf < 8; nf++) {
            int cl = warp_n * 64 + nf * 8 + tg * 2;
            int col = bn + cl;
            float f00 = fmaf(acc[mf][nf][0], ssc[cl],     sof[cl]);
            float f01 = fmaf(acc[mf][nf][1], ssc[cl + 1], sof[cl + 1]);
            float f10 = fmaf(acc[mf][nf][2], ssc[cl],     sof[cl]);
            float f11 = fmaf(acc[mf][nf][3], ssc[cl + 1], sof[cl + 1]);
            __half2 hA = __halves2half2(f00 >= 0.f ? hp1 : hm1, f01 >= 0.f ? hp1 : hm1);
            __half2 hB = __halves2half2(f10 >= 0.f ? hp1 : hm1, f11 >= 0.f ? hp1 : hm1);
            *(__half2*)&g_a2h[(size_t)row * H + col]       = hA;
            *(__half2*)&g_a2h[(size_t)(row + 8) * H + col] = hB;
        }
    }
}

// ---------------- fc2: fp16-acc GEMM, epilogue -> fp16 +-1 (g_a3h) ----------
__global__ __launch_bounds__(128, 3)
void fc2_gemm() {
    extern __shared__ char smem[];
    const uint32_t sb = smem_u32(smem);
    const int tid = threadIdx.x;
    const int wid = tid >> 5, lane = tid & 31;
    const int warp_m = wid >> 1, warp_n = wid & 1;
    const int bn = blockIdx.x * TN, bm = blockIdx.y * TM;

    float* ssc = (float*)(smem);
    float* sof = (float*)(smem + 512);
    ssc[tid] = g_sc2[bn + tid]; sof[tid] = g_of2[bn + tid];

    const char* Abase = (const char*)g_a2h + (size_t)bm * (H * 2);
    const char* Bbase = (const char*)g_w2h + (size_t)bn * (H * 2);

    uint32_t acc[4][8][2];
#pragma unroll
    for (int i = 0; i < 4; i++)
#pragma unroll
        for (int j = 0; j < 8; j++) { acc[i][j][0] = 0u; acc[i][j][1] = 0u; }

    auto load_stage = [&](int s, int buf) {
        size_t kb = (size_t)s * 128;
        uint32_t adst = sb + A_OFF(buf), bdst = sb + B_OFF(buf);
#pragma unroll
        for (int i = 0; i < 8; i++) {
            int idx = i * 128 + tid;
            int row = idx >> 3, c = idx & 7;
            uint32_t off = SWZ((uint32_t)(row * 128 + c * 16));
            const char* srcA = Abase + (size_t)row * (H * 2) + kb + c * 16;
            const char* srcB = Bbase + (size_t)row * (H * 2) + kb + c * 16;
            asm volatile("cp.async.cg.shared.global [%0], [%1], 16;" :: "r"(adst + off), "l"(srcA));
            asm volatile("cp.async.cg.shared.global [%0], [%1], 16;" :: "r"(bdst + off), "l"(srcB));
        }
        asm volatile("cp.async.commit_group;");
    };

    auto compute = [&](int buf) {
        uint32_t ab = sb + A_OFF(buf), bb = sb + B_OFF(buf);
#pragma unroll
        for (int ks = 0; ks < 4; ks++) {
            uint32_t a[4][4], bf[4][4];
            const int kk = ks * 16 + (lane >> 4) * 8;
            const int mrow = warp_m * 64 + (lane & 15);
            const int nrow = warp_n * 64 + (lane & 15);
#pragma unroll
            for (int mf = 0; mf < 4; mf++) {
                uint32_t addr = ab + SWZ((uint32_t)((mrow + mf * 16) * 128 + kk * 2));
                asm volatile("ldmatrix.sync.aligned.m8n8.x4.shared.b16 {%0,%1,%2,%3}, [%4];"
                    : "=r"(a[mf][0]), "=r"(a[mf][1]), "=r"(a[mf][2]), "=r"(a[mf][3]) : "r"(addr));
            }
#pragma unroll
            for (int p = 0; p < 4; p++) {
                uint32_t addr = bb + SWZ((uint32_t)((nrow + p * 16) * 128 + kk * 2));
                asm volatile("ldmatrix.sync.aligned.m8n8.x4.shared.b16 {%0,%1,%2,%3}, [%4];"
                    : "=r"(bf[p][0]), "=r"(bf[p][1]), "=r"(bf[p][2]), "=r"(bf[p][3]) : "r"(addr));
            }
#pragma unroll
            for (int mf = 0; mf < 4; mf++)
#pragma unroll
                for (int nf = 0; nf < 8; nf++) {
                    uint32_t b0 = bf[nf >> 1][nf & 1], b1 = bf[nf >> 1][(nf & 1) + 2];
                    asm volatile(
                        "mma.sync.aligned.m16n8k16.row.col.f16.f16.f16.f16 "
                        "{%0,%1}, {%2,%3,%4,%5}, {%6,%7}, {%0,%1};"
                        : "+r"(acc[mf][nf][0]), "+r"(acc[mf][nf][1])
                        : "r"(a[mf][0]), "r"(a[mf][1]), "r"(a[mf][2]), "r"(a[mf][3]),
                          "r"(b0), "r"(b1));
                }
        }
    };

    load_stage(0, 0);
    for (int s = 0; s < NC2; s++) {
        if (s + 1 < NC2) load_stage(s + 1, (s + 1) & 1);
        if (s + 1 < NC2) asm volatile("cp.async.wait_group 1;");
        else             asm volatile("cp.async.wait_group 0;");
        __syncthreads();
        compute(s & 1);
        __syncthreads();
    }

    const int tg = lane & 3, gid = lane >> 2;
    const __half hp1 = __float2half(1.f), hm1 = __float2half(-1.f);
#pragma unroll
    for (int mf = 0; mf < 4; mf++) {
        int row = bm + warp_m * 64 + mf * 16 + gid;
#pragma unroll
        for (int nf = 0; nf < 8; nf++) {
            int cl = warp_n * 64 + nf * 8 + tg * 2;
            int col = bn + cl;
            float2 fa = __half22float2(*(__half2*)&acc[mf][nf][0]);
            float2 fb = __half22float2(*(__half2*)&acc[mf][nf][1]);
            float f00 = fmaf(fa.x, ssc[cl],     sof[cl]);
            float f01 = fmaf(fa.y, ssc[cl + 1], sof[cl + 1]);
            float f10 = fmaf(fb.x, ssc[cl],     sof[cl]);
            float f11 = fmaf(fb.y, ssc[cl + 1], sof[cl + 1]);
            __half2 hA = __halves2half2(f00 >= 0.f ? hp1 : hm1, f01 >= 0.f ? hp1 : hm1);
            __half2 hB = __halves2half2(f10 >= 0.f ? hp1 : hm1, f11 >= 0.f ? hp1 : hm1);
            *(__half2*)&g_a3h[(size_t)row * H + col]       = hA;
            *(__half2*)&g_a3h[(size_t)(row + 8) * H + col] = hB;
        }
    }
}

// ---------------- fc3: fp16-acc GEMM + fused partial-fc4 epilogue -----------
#define FC3_SMEM (66560 + C * TN * 4)   // + W4 tile [10][128]

__global__ __launch_bounds__(128, 3)
void fc3_gemm(const float* __restrict__ W4) {
    extern __shared__ char smem[];
    const uint32_t sb = smem_u32(smem);
    const int tid = threadIdx.x;
    const int wid = tid >> 5, lane = tid & 31;
    const int warp_m = wid >> 1, warp_n = wid & 1;
    const int bn = blockIdx.x * TN, bm = blockIdx.y * TM;

    float* ssc = (float*)(smem);
    float* sof = (float*)(smem + 512);
    float* sW4 = (float*)(smem + 66560);
    ssc[tid] = g_sc3[bn + tid]; sof[tid] = g_of3[bn + tid];
#pragma unroll
    for (int i = tid; i < C * TN; i += 128) {
        int c = i >> 7, cc = i & 127;
        sW4[i] = W4[c * H + bn + cc];
    }

    const char* Abase = (const char*)g_a3h + (size_t)bm * (H * 2);
    const char* Bbase = (const char*)g_w3h + (size_t)bn * (H * 2);

    uint32_t acc[4][8][2];
#pragma unroll
    for (int i = 0; i < 4; i++)
#pragma unroll
        for (int j = 0; j < 8; j++) { acc[i][j][0] = 0u; acc[i][j][1] = 0u; }

    auto load_stage = [&](int s, int buf) {
        size_t kb = (size_t)s * 128;
        uint32_t adst = sb + A_OFF(buf), bdst = sb + B_OFF(buf);
#pragma unroll
        for (int i = 0; i < 8; i++) {
            int idx = i * 128 + tid;
            int row = idx >> 3, c = idx & 7;
            uint32_t off = SWZ((uint32_t)(row * 128 + c * 16));
            const char* srcA = Abase + (size_t)row * (H * 2) + kb + c * 16;
            const char* srcB = Bbase + (size_t)row * (H * 2) + kb + c * 16;
            asm volatile("cp.async.cg.shared.global [%0], [%1], 16;" :: "r"(adst + off), "l"(srcA));
            asm volatile("cp.async.cg.shared.global [%0], [%1], 16;" :: "r"(bdst + off), "l"(srcB));
        }
        asm volatile("cp.async.commit_group;");
    };

    auto compute = [&](int buf) {
        uint32_t ab = sb + A_OFF(buf), bb = sb + B_OFF(buf);
#pragma unroll
        for (int ks = 0; ks < 4; ks++) {
            uint32_t a[4][4], bf[4][4];
            const int kk = ks * 16 + (lane >> 4) * 8;
            const int mrow = warp_m * 64 + (lane & 15);
            const int nrow = warp_n * 64 + (lane & 15);
#pragma unroll
            for (int mf = 0; mf < 4; mf++) {
                uint32_t addr = ab + SWZ((uint32_t)((mrow + mf * 16) * 128 + kk * 2));
                asm volatile("ldmatrix.sync.aligned.m8n8.x4.shared.b16 {%0,%1,%2,%3}, [%4];"
                    : "=r"(a[mf][0]), "=r"(a[mf][1]), "=r"(a[mf][2]), "=r"(a[mf][3]) : "r"(addr));
            }
#pragma unroll
            for (int p = 0; p < 4; p++) {
                uint32_t addr = bb + SWZ((uint32_t)((nrow + p * 16) * 128 + kk * 2));
                asm volatile("ldmatrix.sync.aligned.m8n8.x4.shared.b16 {%0,%1,%2,%3}, [%4];"
                    : "=r"(bf[p][0]), "=r"(bf[p][1]), "=r"(bf[p][2]), "=r"(bf[p][3]) : "r"(addr));
            }
#pragma unroll
            for (int mf = 0; mf < 4; mf++)
#pragma unroll
                for (int nf = 0; nf < 8; nf++) {
                    uint32_t b0 = bf[nf >> 1][nf & 1], b1 = bf[nf >> 1][(nf & 1) + 2];
                    asm volatile(
                        "mma.sync.aligned.m16n8k16.row.col.f16.f16.f16.f16 "
                        "{%0,%1}, {%2,%3,%4,%5}, {%6,%7}, {%0,%1};"
                        : "+r"(acc[mf][nf][0]), "+r"(acc[mf][nf][1])
                        : "r"(a[mf][0]), "r"(a[mf][1]), "r"(a[mf][2]), "r"(a[mf][3]),
                          "r"(b0), "r"(b1));
                }
        }
    };

    load_stage(0, 0);
    for (int s = 0; s < NC2; s++) {
        if (s + 1 < NC2) load_stage(s + 1, (s + 1) & 1);
        if (s + 1 < NC2) asm volatile("cp.async.wait_group 1;");
        else             asm volatile("cp.async.wait_group 0;");
        __syncthreads();
        compute(s & 1);
        __syncthreads();
    }

    // epilogue: BN + hardtanh + partial fc4 dot over this CTA's 128 columns
    const int tg = lane & 3, gid = lane >> 2;
    const size_t pbase = (size_t)(blockIdx.x * 2 + warp_n) * B * C;
#pragma unroll
    for (int mf = 0; mf < 4; mf++) {
        int r0 = bm + warp_m * 64 + mf * 16 + gid;
        float plg0[C], plg1[C];
#pragma unroll
        for (int c = 0; c < C; c++) { plg0[c] = 0.f; plg1[c] = 0.f; }
#pragma unroll
        for (int nf = 0; nf < 8; nf++) {
            int cl = warp_n * 64 + nf * 8 + tg * 2;
            float2 fa = __half22float2(*(__half2*)&acc[mf][nf][0]);
            float2 fb = __half22float2(*(__half2*)&acc[mf][nf][1]);
            float h00 = fminf(fmaxf(fmaf(fa.x, ssc[cl],     sof[cl]),     -1.f), 1.f);
            float h01 = fminf(fmaxf(fmaf(fa.y, ssc[cl + 1], sof[cl + 1]), -1.f), 1.f);
            float h10 = fminf(fmaxf(fmaf(fb.x, ssc[cl],     sof[cl]),     -1.f), 1.f);
            float h11 = fminf(fmaxf(fmaf(fb.y, ssc[cl + 1], sof[cl + 1]), -1.f), 1.f);
#pragma unroll
            for (int c = 0; c < C; c++) {
                float w0 = sW4[c * TN + cl], w1 = sW4[c * TN + cl + 1];
                plg0[c] += h00 * w0 + h01 * w1;
                plg1[c] += h10 * w0 + h11 * w1;
            }
        }
#pragma unroll
        for (int c = 0; c < C; c++) {
            plg0[c] += __shfl_xor_sync(0xffffffffu, plg0[c], 1);
            plg0[c] += __shfl_xor_sync(0xffffffffu, plg0[c], 2);
            plg1[c] += __shfl_xor_sync(0xffffffffu, plg1[c], 1);
            plg1[c] += __shfl_xor_sync(0xffffffffu, plg1[c], 2);
        }
        if (tg == 0) {
#pragma unroll
            for (int c = 0; c < C; c++) {
                g_plog[pbase + (size_t)r0 * C + c]       = plg0[c];
                g_plog[pbase + (size_t)(r0 + 8) * C + c] = plg1[c];
            }
        }
    }
}

// ---------------- fc4_soft: sum 12 partials + b4 + log_softmax --------------
__global__ __launch_bounds__(256)
void fc4_soft(const float* __restrict__ b4, float* __restrict__ out) {
    int w = blockIdx.x * 256 + threadIdx.x;
    float lg[C];
#pragma unroll
    for (int c = 0; c < C; c++) lg[c] = b4[c];
#pragma unroll
    for (int p = 0; p < NPART; p++) {
        const float* src = &g_plog[(size_t)p * B * C + (size_t)w * C];
#pragma unroll
        for (int c2 = 0; c2 < C / 2; c2++) {
            float2 v = *(const float2*)&src[c2 * 2];
            lg[c2 * 2]     += v.x;
            lg[c2 * 2 + 1] += v.y;
        }
    }
    float mx = -3.402823466e+38f;
#pragma unroll
    for (int c = 0; c < C; c++) mx = fmaxf(mx, lg[c]);
    float s = 0.f;
#pragma unroll
    for (int c = 0; c < C; c++) s += expf(lg[c] - mx);
    float lse = logf(s);
#pragma unroll
    for (int c2 = 0; c2 < C / 2; c2++) {
        float2 v;
        v.x = lg[c2 * 2] - mx - lse;
        v.y = lg[c2 * 2 + 1] - mx - lse;
        *(float2*)&out[(size_t)w * C + c2 * 2] = v;
    }
}

// ---------------- launch (fc1_gemm is launch #4 -> profiled) ----------------
extern "C" void kernel_launch(void* const* d_in, const int* in_sizes, int n_in,
                              void* d_out, int out_size) {
    const float* x   = (const float*)d_in[0];
    const float* W1  = (const float*)d_in[1];
    const float* b1  = (const float*)d_in[2];
    const float* W2  = (const float*)d_in[3];
    const float* b2  = (const float*)d_in[4];
    const float* W3  = (const float*)d_in[5];
    const float* b3  = (const float*)d_in[6];
    const float* W4  = (const float*)d_in[7];
    const float* b4  = (const float*)d_in[8];
    const float* g1  = (const float*)d_in[9];
    const float* be1 = (const float*)d_in[10];
    const float* m1  = (const float*)d_in[11];
    const float* v1  = (const float*)d_in[12];
    const float* g2  = (const float*)d_in[13];
    const float* be2 = (const float*)d_in[14];
    const float* m2  = (const float*)d_in[15];
    const float* v2  = (const float*)d_in[16];
    const float* g3  = (const float*)d_in[17];
    const float* be3 = (const float*)d_in[18];
    const float* m3  = (const float*)d_in[19];
    const float* v3  = (const float*)d_in[20];
    float* out = (float*)d_out;

    cudaFuncSetAttribute(fc1_gemm, cudaFuncAttributeMaxDynamicSharedMemorySize, GEMM_SMEM);
    cudaFuncSetAttribute(fc2_gemm, cudaFuncAttributeMaxDynamicSharedMemorySize, GEMM_SMEM);
    cudaFuncSetAttribute(fc3_gemm, cudaFuncAttributeMaxDynamicSharedMemorySize, FC3_SMEM);

    int w23Threads = 2 * H * 192 + H;
    prep_w23s<<<(w23Threads + 255) / 256, 256>>>(W2, W3,
        b1, g1, m1, be1, v1, b2, g2, m2, be2, v2, b3, g3, m3, be3, v3);
    prep_x<<<B, 224>>>(x);
    prep_w1<<<H, 224>>>(W1);

    fc1_gemm<<<dim3(H / TN, B / TM), 128, GEMM_SMEM>>>();     // launch #4 (profiled)
    fc2_gemm<<<dim3(H / TN, B / TM), 128, GEMM_SMEM>>>();
    fc3_gemm<<<dim3(H / TN, B / TM), 128, FC3_SMEM>>>(W4);
    fc4_soft<<<B / 256, 256>>>(b4, out);
}